// round 5
// baseline (speedup 1.0000x reference)
#include <cuda_runtime.h>
#include <cuda_bf16.h>

#define BATCH 256
#define NRET  100      // stored retrieval slots per row
#define RNUM  80       // RETRIEVAL_NUM actually used
#define DIM   768
#define DF4   (DIM / 4)   // 192 float4 per feature row
#define THRESH 0.5f

// Scratch: per-(b, packed-slot) source index, -1 for zero-fill slots.
__device__ int d_src[BATCH * RNUM];

// Output layout (concatenation, all f32 row-major):
//   vis_packed [B,80,768] | txt_packed [B,80,768] |
//   text_mask [B,81] | img_mask [B,81] | rr_mod [B,80] | labels [B,80]

// ---------------------------------------------------------------------------
// Kernel A: build the permutation table + all small outputs. One block per
// batch row; warp 0 does a ballot-based stable compaction of the 80 flags.
// ---------------------------------------------------------------------------
__global__ __launch_bounds__(128)
void rrcp_index_kernel(const float* __restrict__ labels,
                       const float* __restrict__ rr,
                       float* __restrict__ out)
{
    const int b = blockIdx.x;
    const int t = threadIdx.x;
    const int lane = t & 31;

    __shared__ int s_cnt;
    __shared__ int s_anyge;

    if (t < 32) {
        int base = 0;
        unsigned anyge = 0;
        #pragma unroll
        for (int chunk = 0; chunk < 3; chunk++) {
            const int i = chunk * 32 + lane;
            const float v = (i < RNUM) ? __ldg(&rr[(size_t)b * NRET + i]) : 0.0f;
            const bool f = (i < RNUM) && (v > THRESH);
            const unsigned m = __ballot_sync(0xffffffffu, f);
            anyge |= __ballot_sync(0xffffffffu, (i < RNUM) && (v >= THRESH));
            if (f)
                d_src[b * RNUM + base + __popc(m & ((1u << lane) - 1u))] = i;
            base += __popc(m);
        }
        if (lane == 0) { s_cnt = base; s_anyge = (anyge != 0); }
    }
    __syncthreads();
    const int cnt = s_cnt;

    // Fill unused packed slots with -1
    for (int p = cnt + t; p < RNUM; p += 128)
        d_src[b * RNUM + p] = -1;

    // Small outputs
    float* __restrict__ text_mask = out + 2 * (size_t)BATCH * RNUM * DIM;
    float* __restrict__ img_mask  = text_mask + (size_t)BATCH * (RNUM + 1);
    float* __restrict__ rr_mod    = img_mask  + (size_t)BATCH * (RNUM + 1);
    float* __restrict__ lab_out   = rr_mod    + (size_t)BATCH * RNUM;

    if (t <= RNUM) {
        const float m = (t <= cnt) ? 1.0f : 0.0f;
        text_mask[b * (RNUM + 1) + t] = m;
        img_mask [b * (RNUM + 1) + t] = (b == BATCH - 1) ? m : 1.0f;
    }
    if (t < RNUM) {
        const float v = __ldg(&rr[(size_t)b * NRET + t]);
        float m = (v < THRESH) ? 0.0f : v;      // where(rr<0.5, 0, rr)
        if (t == 0 && !s_anyge) m = 1.0f;       // all-zero row fix at col 0
        rr_mod [b * RNUM + t] = m;
        lab_out[b * RNUM + t] = labels[(size_t)b * NRET + t];
    }
}

// ---------------------------------------------------------------------------
// Kernel B: warp-autonomous streaming copy. Each WARP owns 4 consecutive
// packed slots of one batch row. One int4 broadcast fetches the 4 source
// indices; per slot each lane moves 6 float4 per tensor (12 independent
// LDG.128 in flight, then 12 evict-first STG.128). No smem, no barriers.
// ---------------------------------------------------------------------------
#define SLOTS_PER_WARP 4
#define GROUPS (RNUM / SLOTS_PER_WARP)     // 20 per batch row
#define WARPS_PER_BLOCK 4

__global__ __launch_bounds__(32 * WARPS_PER_BLOCK)
void rrcp_copy_kernel(const float* __restrict__ vis,
                      const float* __restrict__ txt,
                      float* __restrict__ out)
{
    const int wg   = blockIdx.x * WARPS_PER_BLOCK + (threadIdx.x >> 5);
    const int lane = threadIdx.x & 31;
    const int b    = wg / GROUPS;
    const int j0   = (wg % GROUPS) * SLOTS_PER_WARP;

    // 4 slot indices in one 16B broadcast load
    const int4 idx = __ldg(reinterpret_cast<const int4*>(&d_src[b * RNUM + j0]));
    int srcs[SLOTS_PER_WARP] = {idx.x, idx.y, idx.z, idx.w};

    const float4* __restrict__ vbase =
        reinterpret_cast<const float4*>(vis) + (size_t)b * NRET * DF4;
    const float4* __restrict__ tbase =
        reinterpret_cast<const float4*>(txt) + (size_t)b * NRET * DF4;
    float4* __restrict__ ov = reinterpret_cast<float4*>(out)
                              + ((size_t)b * RNUM + j0) * DF4;
    float4* __restrict__ ot = ov + (size_t)BATCH * RNUM * DF4;

    #pragma unroll
    for (int k = 0; k < SLOTS_PER_WARP; k++) {
        const int src = srcs[k];
        float4 va[6], ta[6];
        if (src >= 0) {
            const float4* __restrict__ sv = vbase + (size_t)src * DF4;
            const float4* __restrict__ st = tbase + (size_t)src * DF4;
            #pragma unroll
            for (int u = 0; u < 6; u++) va[u] = __ldg(&sv[lane + u * 32]);
            #pragma unroll
            for (int u = 0; u < 6; u++) ta[u] = __ldg(&st[lane + u * 32]);
        } else {
            const float4 z = make_float4(0.f, 0.f, 0.f, 0.f);
            #pragma unroll
            for (int u = 0; u < 6; u++) { va[u] = z; ta[u] = z; }
        }
        float4* __restrict__ dv = ov + (size_t)k * DF4;
        float4* __restrict__ dt = ot + (size_t)k * DF4;
        #pragma unroll
        for (int u = 0; u < 6; u++) __stcs(&dv[lane + u * 32], va[u]);
        #pragma unroll
        for (int u = 0; u < 6; u++) __stcs(&dt[lane + u * 32], ta[u]);
    }
}

extern "C" void kernel_launch(void* const* d_in, const int* in_sizes, int n_in,
                              void* d_out, int out_size)
{
    // metadata order:
    // 0: mean_pooling_vec (unused)
    // 1: merge_text_vec   (unused)
    // 2: retrieved_visual_feature_embedding_cls [B,100,1,768]
    // 3: retrieved_textual_feature_embedding    [B,100,1,768]
    // 4: retrieved_label_list [B,100]
    // 5: RRCP                 [B,100]
    const float* vis    = (const float*)d_in[2];
    const float* txt    = (const float*)d_in[3];
    const float* labels = (const float*)d_in[4];
    const float* rr     = (const float*)d_in[5];
    float* out = (float*)d_out;

    rrcp_index_kernel<<<BATCH, 128>>>(labels, rr, out);

    const int total_warps = BATCH * GROUPS;                   // 5120
    const int blocks = total_warps / WARPS_PER_BLOCK;         // 1280
    rrcp_copy_kernel<<<blocks, 32 * WARPS_PER_BLOCK>>>(vis, txt, out);
}

// round 6
// speedup vs baseline: 1.0879x; 1.0879x over previous
#include <cuda_runtime.h>
#include <cuda_bf16.h>

#define BATCH 256
#define NRET  100      // stored retrieval slots per row
#define RNUM  80       // RETRIEVAL_NUM actually used
#define DIM   768
#define DF4   (DIM / 4)   // 192 float4 per feature row
#define THRESH 0.5f

#define SLOTS_PER_WARP 2
#define GROUPS (RNUM / SLOTS_PER_WARP)      // 40 groups per batch row
#define WARPS_PER_BLOCK 8                   // 256 threads
#define TOTAL_WARPS (BATCH * GROUPS)        // 10240
#define NBLOCKS (TOTAL_WARPS / WARPS_PER_BLOCK)  // 1280

// Output layout (concatenation, all f32 row-major):
//   vis_packed [B,80,768] | txt_packed [B,80,768] |
//   text_mask [B,81] | img_mask [B,81] | rr_mod [B,80] | labels [B,80]

__global__ __launch_bounds__(32 * WARPS_PER_BLOCK)
void rrcp_fused_kernel(const float* __restrict__ vis,
                       const float* __restrict__ txt,
                       const float* __restrict__ labels,
                       const float* __restrict__ rr,
                       float* __restrict__ out)
{
    const int w    = blockIdx.x * WARPS_PER_BLOCK + (threadIdx.x >> 5);
    const int lane = threadIdx.x & 31;
    const int b    = w / GROUPS;
    const int grp  = w % GROUPS;
    const int j0   = grp * SLOTS_PER_WARP;

    // ---- warp-local stable compaction scan over the 80 rr flags ----
    const float* __restrict__ rrow = rr + (size_t)b * NRET;
    int base = 0;
    unsigned anyge = 0;
    int s0 = -1, s1 = -1;
    #pragma unroll
    for (int chunk = 0; chunk < 3; chunk++) {
        const int i = chunk * 32 + lane;
        const float v = (i < RNUM) ? __ldg(&rrow[i]) : 0.0f;
        const bool f = (i < RNUM) && (v > THRESH);
        const unsigned m = __ballot_sync(0xffffffffu, f);
        anyge |= __ballot_sync(0xffffffffu, (i < RNUM) && (v >= THRESH));
        const int pos = base + __popc(m & ((1u << lane) - 1u));
        const unsigned m0 = __ballot_sync(0xffffffffu, f && pos == j0);
        const unsigned m1 = __ballot_sync(0xffffffffu, f && pos == j0 + 1);
        if (m0) s0 = __shfl_sync(0xffffffffu, i, __ffs(m0) - 1);
        if (m1) s1 = __shfl_sync(0xffffffffu, i, __ffs(m1) - 1);
        base += __popc(m);
    }
    const int cnt = base;   // uniform across warp

    // ---- streaming copy: 2 packed slots, per-tensor pipelined ----
    const float4* __restrict__ vbase =
        reinterpret_cast<const float4*>(vis) + (size_t)b * NRET * DF4;
    const float4* __restrict__ tbase =
        reinterpret_cast<const float4*>(txt) + (size_t)b * NRET * DF4;
    float4* __restrict__ ov = reinterpret_cast<float4*>(out)
                              + ((size_t)b * RNUM + j0) * DF4;
    float4* __restrict__ ot = ov + (size_t)BATCH * RNUM * DF4;

    const int srcs[SLOTS_PER_WARP] = { s0, s1 };
    #pragma unroll
    for (int k = 0; k < SLOTS_PER_WARP; k++) {
        const int src = srcs[k];
        float4* __restrict__ dv = ov + (size_t)k * DF4;
        float4* __restrict__ dt = ot + (size_t)k * DF4;
        if (src >= 0) {
            const float4* __restrict__ sv = vbase + (size_t)src * DF4;
            const float4* __restrict__ st = tbase + (size_t)src * DF4;
            float4 buf[6];
            #pragma unroll
            for (int u = 0; u < 6; u++) buf[u] = __ldg(&sv[lane + u * 32]);
            #pragma unroll
            for (int u = 0; u < 6; u++) __stcs(&dv[lane + u * 32], buf[u]);
            #pragma unroll
            for (int u = 0; u < 6; u++) buf[u] = __ldg(&st[lane + u * 32]);
            #pragma unroll
            for (int u = 0; u < 6; u++) __stcs(&dt[lane + u * 32], buf[u]);
        } else {
            const float4 z = make_float4(0.f, 0.f, 0.f, 0.f);
            #pragma unroll
            for (int u = 0; u < 6; u++) __stcs(&dv[lane + u * 32], z);
            #pragma unroll
            for (int u = 0; u < 6; u++) __stcs(&dt[lane + u * 32], z);
        }
    }

    // ---- group 0 warps emit the small outputs for their batch row ----
    if (grp == 0) {
        float* __restrict__ text_mask = out + 2 * (size_t)BATCH * RNUM * DIM;
        float* __restrict__ img_mask  = text_mask + (size_t)BATCH * (RNUM + 1);
        float* __restrict__ rr_mod    = img_mask  + (size_t)BATCH * (RNUM + 1);
        float* __restrict__ lab_out   = rr_mod    + (size_t)BATCH * RNUM;

        #pragma unroll
        for (int i = lane; i <= RNUM; i += 32) {
            const float m = (i <= cnt) ? 1.0f : 0.0f;
            text_mask[b * (RNUM + 1) + i] = m;
            img_mask [b * (RNUM + 1) + i] = (b == BATCH - 1) ? m : 1.0f;
        }
        #pragma unroll
        for (int i = lane; i < RNUM; i += 32) {
            const float v = __ldg(&rrow[i]);
            float m = (v < THRESH) ? 0.0f : v;      // where(rr<0.5, 0, rr)
            if (i == 0 && anyge == 0u) m = 1.0f;    // all-zero row fix at col 0
            rr_mod [b * RNUM + i] = m;
            lab_out[b * RNUM + i] = __ldg(&labels[(size_t)b * NRET + i]);
        }
    }
}

extern "C" void kernel_launch(void* const* d_in, const int* in_sizes, int n_in,
                              void* d_out, int out_size)
{
    // metadata order:
    // 0: mean_pooling_vec (unused)
    // 1: merge_text_vec   (unused)
    // 2: retrieved_visual_feature_embedding_cls [B,100,1,768]
    // 3: retrieved_textual_feature_embedding    [B,100,1,768]
    // 4: retrieved_label_list [B,100]
    // 5: RRCP                 [B,100]
    const float* vis    = (const float*)d_in[2];
    const float* txt    = (const float*)d_in[3];
    const float* labels = (const float*)d_in[4];
    const float* rr     = (const float*)d_in[5];
    float* out = (float*)d_out;

    rrcp_fused_kernel<<<NBLOCKS, 32 * WARPS_PER_BLOCK>>>(vis, txt, labels, rr, out);
}